// round 16
// baseline (speedup 1.0000x reference)
#include <cuda_runtime.h>
#include <cstdint>

// LSTM(B=8192, T=1024, H=10, in=1) -> final cell state c_T -> Linear(10,1).
//
// R15: PHASE-SKEWED two-chain software pipeline.
// Convoy diagnosis: identical warps re-synced by the recurrence hit the
// same pipe phase simultaneously (all-FMA, then all-MUFU, then all-MIO);
// wall ~= sum of phase times with every pipe <50% busy (matches R13: 204
// fma + 184 mufu + ~100 mio ~= 460 cyc/step measured).
// Fix: each warp carries TWO chains (A: groups 0-2, B: groups 3-5) skewed
// by half a step:  stage2_A (tanh/update, MUFU) || stage1_B (acc, FMA),
// then stage2_B || stage1_A(t+1). Adjacent independent blocks let ptxas
// overlap MUFU with FMA. 1366 single-warp blocks, ~same chip instrs/step
// as champion R13 -- the bet is purely on issue-rate via phase mixing.
//
// Math identical to R13: dup-h table, gate-pair f32x2 accumulation,
// f32 tanh.approx, sigma folded into pre-scaled weights, h' = 2h,
// 80B group stride (aligned, broadcast-conflict-free), no per-step sync.

#define B_TOT 8192
#define T_LEN 1024
#define HID   10
#define GPW   3                    // groups per chain
#define BPW   (2 * GPW)            // 6 batches per warp
#define GSTRIDE 20                 // floats per group region (80B)

typedef unsigned long long ull;

__device__ __forceinline__ ull pack2(float x, float y) {
    ull r;
    asm("mov.b64 %0, {%1, %2};" : "=l"(r) : "f"(x), "f"(y));
    return r;
}
__device__ __forceinline__ ull ffma2(ull a, ull b, ull c) {
    ull d;
    asm("fma.rn.f32x2 %0, %1, %2, %3;" : "=l"(d) : "l"(a), "l"(b), "l"(c));
    return d;
}
__device__ __forceinline__ float ftanh(float x) {
    float r;
    asm("tanh.approx.f32 %0, %1;" : "=f"(r) : "f"(x));
    return r;
}
__device__ __forceinline__ void lds_v2b64(uint32_t addr, ull& a, ull& b) {
    asm volatile("ld.shared.v2.b64 {%0, %1}, [%2];" : "=l"(a), "=l"(b) : "r"(addr));
}
__device__ __forceinline__ void sts_dup(uint32_t addr, float v) {
    asm volatile("st.shared.v2.f32 [%0], {%1, %1};" :: "r"(addr), "f"(v) : "memory");
}
__device__ __forceinline__ uint32_t smem_u32(const void* p) {
    uint32_t a;
    asm("{ .reg .u64 t; cvta.to.shared.u64 t, %1; cvt.u32.u64 %0, t; }"
        : "=r"(a) : "l"(p));
    return a;
}

struct Weights {
    ull wif[HID], wgo[HID];
    ull wxif, wxgo, bif, bgo;
};

// stage 1: gate-pair accumulation (FMA phase)
__device__ __forceinline__ void stage1(const Weights& W, const ull* hd, ull xx,
                                       ull& acc_if, ull& acc_go) {
    acc_if = ffma2(xx, W.wxif, W.bif);
    acc_go = ffma2(xx, W.wxgo, W.bgo);
#pragma unroll
    for (int k = 0; k < HID; k++) {
        acc_if = ffma2(W.wif[k], hd[k], acc_if);
        acc_go = ffma2(W.wgo[k], hd[k], acc_go);
    }
}

// stage 2: activations + state update + store (MUFU phase)
__device__ __forceinline__ void stage2(ull acc_if, ull acc_go, float& c,
                                       uint32_t wr, bool active) {
    const float2 gif = *reinterpret_cast<const float2*>(&acc_if);
    const float2 ggo = *reinterpret_cast<const float2*>(&acc_go);
    const float ti = ftanh(gif.x);
    const float tf = ftanh(gif.y);
    const float tg = ftanh(ggo.x);
    const float to = ftanh(ggo.y);
    const float sf = fmaf(0.5f, tf, 0.5f);
    const float si = fmaf(0.5f, ti, 0.5f);
    c = fmaf(sf, c, si * tg);
    const float tc = ftanh(c);
    const float hn = fmaf(to, tc, tc);
    if (active) sts_dup(wr, hn);
    asm volatile("" ::: "memory");   // pin STS before subsequent LDS
}

__device__ __forceinline__ void load_table(uint32_t rd, ull* hd) {
    lds_v2b64(rd +  0, hd[0], hd[1]);
    lds_v2b64(rd + 16, hd[2], hd[3]);
    lds_v2b64(rd + 32, hd[4], hd[5]);
    lds_v2b64(rd + 48, hd[6], hd[7]);
    lds_v2b64(rd + 64, hd[8], hd[9]);
}

__global__ __launch_bounds__(32)
void lstm_lin_kernel(const float* __restrict__ x,       // [B, T, 1]
                     const float* __restrict__ W_ih,    // [4H, 1]
                     const float* __restrict__ W_hh,    // [4H, H]
                     const float* __restrict__ b_ih,    // [4H]
                     const float* __restrict__ b_hh,    // [4H]
                     const float* __restrict__ W_lin,   // [1, H]
                     const float* __restrict__ b_lin,   // [1]
                     float* __restrict__ out)           // [B, 1]
{
    // [parity][chain][group][20 floats]; dup pairs at float offsets 2r,2r+1
    __shared__ float hbuf[2][2][GPW][GSTRIDE];

    const int wlane = threadIdx.x;
    const int group = wlane / HID;           // 0..2 active; 3 => lanes 30,31
    const int r     = wlane - group * HID;   // unit 0..9
    const int base  = group * HID;
    const bool active = (group < GPW);
    const int sgrp   = active ? group : 0;

    const int batchA = blockIdx.x * BPW + group;         // chain A
    const int batchB = blockIdx.x * BPW + GPW + group;   // chain B
    const bool validA = active && (batchA < B_TOT);
    const bool validB = active && (batchB < B_TOT);
    const int bA = validA ? batchA : 0;
    const int bB = validB ? batchB : 0;

    // ---- shared weights (R13 pre-scaling) ----
    Weights W;
#pragma unroll
    for (int k = 0; k < HID; k++) {
        W.wif[k] = pack2(W_hh[(0 * HID + r) * HID + k] * 0.25f,
                         W_hh[(1 * HID + r) * HID + k] * 0.25f);
        W.wgo[k] = pack2(W_hh[(2 * HID + r) * HID + k] * 0.50f,
                         W_hh[(3 * HID + r) * HID + k] * 0.25f);
    }
    W.wxif = pack2(W_ih[0 * HID + r] * 0.5f, W_ih[1 * HID + r] * 0.5f);
    W.wxgo = pack2(W_ih[2 * HID + r] * 1.0f, W_ih[3 * HID + r] * 0.5f);
    W.bif  = pack2((b_ih[0 * HID + r] + b_hh[0 * HID + r]) * 0.5f,
                   (b_ih[1 * HID + r] + b_hh[1 * HID + r]) * 0.5f);
    W.bgo  = pack2((b_ih[2 * HID + r] + b_hh[2 * HID + r]) * 1.0f,
                   (b_ih[3 * HID + r] + b_hh[3 * HID + r]) * 0.5f);

    float cA = 0.0f, cB = 0.0f;

    const uint32_t smem0 = smem_u32(&hbuf[0][0][0][0]);
    // region index: parity*6 + chain*3 + group, each 80B
    const uint32_t baseA0 = smem0 + (uint32_t)(0 * 6 + 0 * GPW + sgrp) * 80;
    const uint32_t baseB0 = smem0 + (uint32_t)(0 * 6 + 1 * GPW + sgrp) * 80;
    const uint32_t baseA1 = baseA0 + 6 * 80;
    const uint32_t baseB1 = baseB0 + 6 * 80;
    const uint32_t slotA0 = baseA0 + r * 8, slotA1 = baseA1 + r * 8;
    const uint32_t slotB0 = baseB0 + r * 8, slotB1 = baseB1 + r * 8;

    if (active) { sts_dup(slotA0, 0.0f); sts_dup(slotB0, 0.0f); }
    __syncwarp();

    const float4* __restrict__ xrowA =
        reinterpret_cast<const float4*>(x + (size_t)bA * T_LEN);
    const float4* __restrict__ xrowB =
        reinterpret_cast<const float4*>(x + (size_t)bB * T_LEN);

    // ---- prologue: fill the skewed pipeline ----
    ull hdA[HID], hdB[HID];
    load_table(baseA0, hdA);
    load_table(baseB0, hdB);

    float4 bufA = __ldg(&xrowA[0]);
    ull accA_if, accA_go, accB_if, accB_go;
    stage1(W, hdA, pack2(bufA.x, bufA.x), accA_if, accA_go);   // accA(0)

    for (int t4 = 0; t4 < T_LEN / 4; t4++) {
        const float4 bufB = __ldg(&xrowB[t4]);
        const int t4n = (t4 + 1 < T_LEN / 4) ? t4 + 1 : t4;
        const float4 bufAn = __ldg(&xrowA[t4n]);
        const float xBs[4] = {bufB.x, bufB.y, bufB.z, bufB.w};
        const float xAn[4] = {bufA.y, bufA.z, bufA.w, bufAn.x}; // x_A[t+1]

#pragma unroll
        for (int jt = 0; jt < 4; jt++) {
            // step s = t4*4+jt ; reads parity jt&1, writes parity ^1
            const uint32_t wrA = (jt & 1) ? slotA0 : slotA1;
            const uint32_t rdA = (jt & 1) ? baseA0 : baseA1;
            const uint32_t wrB = (jt & 1) ? slotB0 : slotB1;
            const uint32_t rdB = (jt & 1) ? baseB0 : baseB1;

            // A stage2 (MUFU)  --  overlaps with B stage1 (FMA) below
            stage2(accA_if, accA_go, cA, wrA, active);
            load_table(rdA, hdA);                         // h_A(s+1)
            stage1(W, hdB, pack2(xBs[jt], xBs[jt]), accB_if, accB_go);

            // B stage2 (MUFU)  --  overlaps with A stage1(s+1) (FMA)
            stage2(accB_if, accB_go, cB, wrB, active);
            load_table(rdB, hdB);                         // h_B(s+1)
            stage1(W, hdA, pack2(xAn[jt], xAn[jt]), accA_if, accA_go);
        }
        bufA = bufAn;
    }
    // trailing accA(T) is computed and discarded (harmless; reads clamped x)

    // ---- epilogue: out[b] = sum_u c[u] * W_lin[u] + b_lin ----
    const float wl = W_lin[r];
    float pA = cA * wl, pB = cB * wl;
    float sA = pA, sB = pB;
#pragma unroll
    for (int j = 1; j < HID; j++) {
        sA += __shfl_sync(0xffffffffu, pA, base + j);
        sB += __shfl_sync(0xffffffffu, pB, base + j);
    }
    if (validA && r == 0) out[batchA] = sA + b_lin[0];
    if (validB && r == 0) out[batchB] = sB + b_lin[0];
}

extern "C" void kernel_launch(void* const* d_in, const int* in_sizes, int n_in,
                              void* d_out, int out_size) {
    const float* x     = (const float*)d_in[0];
    const float* W_ih  = (const float*)d_in[1];
    const float* W_hh  = (const float*)d_in[2];
    const float* b_ih  = (const float*)d_in[3];
    const float* b_hh  = (const float*)d_in[4];
    const float* W_lin = (const float*)d_in[5];
    const float* b_lin = (const float*)d_in[6];
    float* out = (float*)d_out;

    const int blocks = (B_TOT + BPW - 1) / BPW;   // 1366 single-warp blocks
    lstm_lin_kernel<<<blocks, 32>>>(
        x, W_ih, W_hh, b_ih, b_hh, W_lin, b_lin, out);
}

// round 17
// speedup vs baseline: 1.2085x; 1.2085x over previous
#include <cuda_runtime.h>
#include <cstdint>

// LSTM(B=8192, T=1024, H=10, in=1) -> final cell state c_T -> Linear(10,1).
//
// R16: low-instr AND low-MIO via the SWAP-MERGE accumulation trick.
// Empirical law (11 rounds): wall ~= instrs/(592*rate), rate ~= 0.475 at
// 4 MIO ops/warp-step vs ~0.42 at 6. R13 (37 instr, 6 MIO) and R11
// (46 instr, 4 MIO) tie at ~240-260; this fills the (42 instr, 4 MIO) cell.
//
// Trick: table NON-duplicated (1 STS.32 + 2 LDS.128 + 1 LDS.64 = 4 MIO).
// Loaded pairs hp[j] = (h_2j, h_2j+1). Per gate-pair (i,f) run two accs
// with complementary weight parity:
//   acc_a(if) += (w_i[2j],  w_f[2j+1]) * hp[j]   -> (even-k i, odd-k f)
//   acc_b(fi) += (w_f[2j],  w_i[2j+1]) * hp[j]   -> (even-k f, odd-k i)
// then fadd2(acc_a, swap(acc_b)) = (pre_i, pre_f): ONE swap + ONE fadd2
// per gate-pair (not per k). x & bias folded into acc_a's init ffma2.
//
// Kept from champion R13: 2731 single-warp blocks (3 batches, 10 lanes
// each), f32 tanh.approx, sigma=0.5+0.5*tanh(x/2) folded into pre-scaled
// weights, state h'=2h, double-buffered parity table, no per-step sync.

#define B_TOT 8192
#define T_LEN 1024
#define HID   10
#define GPW   3
#define GSTRIDE 12              // floats per group region (48B, 16B-aligned)

typedef unsigned long long ull;

__device__ __forceinline__ ull pack2(float x, float y) {
    ull r;
    asm("mov.b64 %0, {%1, %2};" : "=l"(r) : "f"(x), "f"(y));
    return r;
}
__device__ __forceinline__ ull ffma2(ull a, ull b, ull c) {
    ull d;
    asm("fma.rn.f32x2 %0, %1, %2, %3;" : "=l"(d) : "l"(a), "l"(b), "l"(c));
    return d;
}
__device__ __forceinline__ ull fmul2(ull a, ull b) {
    ull d;
    asm("mul.rn.f32x2 %0, %1, %2;" : "=l"(d) : "l"(a), "l"(b));
    return d;
}
__device__ __forceinline__ ull fadd2(ull a, ull b) {
    ull d;
    asm("add.rn.f32x2 %0, %1, %2;" : "=l"(d) : "l"(a), "l"(b));
    return d;
}
__device__ __forceinline__ float ftanh(float x) {
    float r;
    asm("tanh.approx.f32 %0, %1;" : "=f"(r) : "f"(x));
    return r;
}
__device__ __forceinline__ void lds_v2b64(uint32_t addr, ull& a, ull& b) {
    asm volatile("ld.shared.v2.b64 {%0, %1}, [%2];" : "=l"(a), "=l"(b) : "r"(addr));
}
__device__ __forceinline__ ull lds_b64(uint32_t addr) {
    ull a;
    asm volatile("ld.shared.b64 %0, [%1];" : "=l"(a) : "r"(addr));
    return a;
}
__device__ __forceinline__ void sts_f32(uint32_t addr, float v) {
    asm volatile("st.shared.f32 [%0], %1;" :: "r"(addr), "f"(v) : "memory");
}
__device__ __forceinline__ uint32_t smem_u32(const void* p) {
    uint32_t a;
    asm("{ .reg .u64 t; cvta.to.shared.u64 t, %1; cvt.u32.u64 %0, t; }"
        : "=r"(a) : "l"(p));
    return a;
}
__device__ __forceinline__ ull swap2(ull v) {
    const float2 f = *reinterpret_cast<const float2*>(&v);
    return pack2(f.y, f.x);
}

__global__ __launch_bounds__(32)
void lstm_lin_kernel(const float* __restrict__ x,       // [B, T, 1]
                     const float* __restrict__ W_ih,    // [4H, 1]
                     const float* __restrict__ W_hh,    // [4H, H]
                     const float* __restrict__ b_ih,    // [4H]
                     const float* __restrict__ b_hh,    // [4H]
                     const float* __restrict__ W_lin,   // [1, H]
                     const float* __restrict__ b_lin,   // [1]
                     float* __restrict__ out)           // [B, 1]
{
    // [parity][group][12 floats]; non-dup h at float index r.
    __shared__ float hbuf[2][GPW][GSTRIDE];

    const int wlane = threadIdx.x;          // single-warp block
    const int group = wlane / HID;          // 0..2 active; 3 => lanes 30,31
    const int r     = wlane - group * HID;  // unit 0..9
    const int base  = group * HID;
    const bool active = (group < GPW);
    const int sgrp   = active ? group : 0;

    const int gbatch = blockIdx.x * GPW + group;
    const bool valid = active && (gbatch < B_TOT);
    const int b = valid ? gbatch : 0;

    // ---- weights: complementary-parity gate-pairs, pre-scaled ----
    // s_i=s_f=s_o=0.25 on W_hh (sigmoid 0.5 x h'-fold 0.5); s_g=0.5.
    const float SI = 0.25f, SF = 0.25f, SG = 0.50f, SO = 0.25f;
    const float* Wi = W_hh + (0 * HID + r) * HID;
    const float* Wf = W_hh + (1 * HID + r) * HID;
    const float* Wg = W_hh + (2 * HID + r) * HID;
    const float* Wo = W_hh + (3 * HID + r) * HID;

    ull wa_if[5], wb_fi[5], wa_go[5], wb_og[5];
#pragma unroll
    for (int j = 0; j < 5; j++) {
        wa_if[j] = pack2(Wi[2 * j] * SI, Wf[2 * j + 1] * SF);
        wb_fi[j] = pack2(Wf[2 * j] * SF, Wi[2 * j + 1] * SI);
        wa_go[j] = pack2(Wg[2 * j] * SG, Wo[2 * j + 1] * SO);
        wb_og[j] = pack2(Wo[2 * j] * SO, Wg[2 * j + 1] * SG);
    }
    // x & bias folded into acc_a init (sigmoid scale 0.5 on i,f,o; 1.0 on g)
    const ull xw_if = pack2(W_ih[0 * HID + r] * 0.5f, W_ih[1 * HID + r] * 0.5f);
    const ull xw_go = pack2(W_ih[2 * HID + r] * 1.0f, W_ih[3 * HID + r] * 0.5f);
    const ull bb_if = pack2((b_ih[0 * HID + r] + b_hh[0 * HID + r]) * 0.5f,
                            (b_ih[1 * HID + r] + b_hh[1 * HID + r]) * 0.5f);
    const ull bb_go = pack2((b_ih[2 * HID + r] + b_hh[2 * HID + r]) * 1.0f,
                            (b_ih[3 * HID + r] + b_hh[3 * HID + r]) * 0.5f);

    float c = 0.0f;

    const uint32_t smem0 = smem_u32(&hbuf[0][0][0]);
    const uint32_t grp_base0 = smem0 + (uint32_t)sgrp * (GSTRIDE * 4);
    const uint32_t grp_base1 = grp_base0 + GPW * GSTRIDE * 4;   // parity-1
    const uint32_t slot0 = grp_base0 + r * 4;
    const uint32_t slot1 = grp_base1 + r * 4;

    if (active) sts_f32(slot0, 0.0f);
    __syncwarp();

    const float4* __restrict__ xrow =
        reinterpret_cast<const float4*>(x + (size_t)b * T_LEN);

    for (int t4 = 0; t4 < T_LEN / 4; t4++) {
        const float4 xq = __ldg(&xrow[t4]);
        ull xx[4];
        xx[0] = pack2(xq.x, xq.x);
        xx[1] = pack2(xq.y, xq.y);
        xx[2] = pack2(xq.z, xq.z);
        xx[3] = pack2(xq.w, xq.w);

#pragma unroll
        for (int jt = 0; jt < 4; jt++) {
            const uint32_t rd = (jt & 1) ? grp_base1 : grp_base0;
            const uint32_t wr = (jt & 1) ? slot0 : slot1;

            // 3 loads -> 5 pairs hp[j] = (h_2j, h_2j+1)
            ull hp[5];
            lds_v2b64(rd +  0, hp[0], hp[1]);
            lds_v2b64(rd + 16, hp[2], hp[3]);
            hp[4] = lds_b64(rd + 32);

            // complementary-parity accumulation
            ull aif = ffma2(xx[jt], xw_if, bb_if);
            ull ago = ffma2(xx[jt], xw_go, bb_go);
            ull bfi = fmul2(wb_fi[0], hp[0]);
            ull bog = fmul2(wb_og[0], hp[0]);
            aif = ffma2(wa_if[0], hp[0], aif);
            ago = ffma2(wa_go[0], hp[0], ago);
#pragma unroll
            for (int j = 1; j < 5; j++) {
                aif = ffma2(wa_if[j], hp[j], aif);
                bfi = ffma2(wb_fi[j], hp[j], bfi);
                ago = ffma2(wa_go[j], hp[j], ago);
                bog = ffma2(wb_og[j], hp[j], bog);
            }

            // merge: (pre_i, pre_f) = aif + swap(bfi); same for (g,o)
            const ull pif = fadd2(aif, swap2(bfi));
            const ull pgo = fadd2(ago, swap2(bog));

            const float2 gif = *reinterpret_cast<const float2*>(&pif);
            const float2 ggo = *reinterpret_cast<const float2*>(&pgo);
            const float ti = ftanh(gif.x);
            const float tf = ftanh(gif.y);
            const float tg = ftanh(ggo.x);
            const float to = ftanh(ggo.y);

            // c = sigma_f*c + sigma_i*tanh_g ; sigma = 0.5 + 0.5*t
            const float sf = fmaf(0.5f, tf, 0.5f);
            const float si = fmaf(0.5f, ti, 0.5f);
            c = fmaf(sf, c, si * tg);

            // h' = 2h = (1 + tanh_o) * tanh(c); scalar store
            const float tc = ftanh(c);
            const float hn = fmaf(to, tc, tc);
            if (active) sts_f32(wr, hn);

            asm volatile("" ::: "memory");   // pin STS(t) before LDS(t+1)
        }
    }

    // ---- epilogue: out[b] = sum_u c[u] * W_lin[u] + b_lin ----
    float part = c * W_lin[r];
    float sum = part;
#pragma unroll
    for (int j = 1; j < HID; j++)
        sum += __shfl_sync(0xffffffffu, part, base + j);

    if (valid && r == 0) {
        out[gbatch] = sum + b_lin[0];
    }
}

extern "C" void kernel_launch(void* const* d_in, const int* in_sizes, int n_in,
                              void* d_out, int out_size) {
    const float* x     = (const float*)d_in[0];
    const float* W_ih  = (const float*)d_in[1];
    const float* W_hh  = (const float*)d_in[2];
    const float* b_ih  = (const float*)d_in[3];
    const float* b_hh  = (const float*)d_in[4];
    const float* W_lin = (const float*)d_in[5];
    const float* b_lin = (const float*)d_in[6];
    float* out = (float*)d_out;

    const int blocks = (B_TOT + GPW - 1) / GPW;   // 2731 single-warp blocks
    lstm_lin_kernel<<<blocks, 32>>>(
        x, W_ih, W_hh, b_ih, b_hh, W_lin, b_lin, out);
}